// round 16
// baseline (speedup 1.0000x reference)
#include <cuda_runtime.h>
#include <cuda_bf16.h>
#include <cstdint>

// Embedding gather: out[r, :] = table[indices[r], :]
// n_rows = B*F = 819200, D = 64 floats (256 B per row).
//
// R15: last sweep point — BLOCK=1024 (512 rows/block, grid=1600), same
// converged structure as the 512-thread optimum (kernel 57.4-58.1us,
// DRAM ~73% = ceiling, traffic at byte floor). Larger CTA = fewer CLC
// dispatch boundaries and longer contiguous write segments per block.
// Expected within noise; certifies the CTA-size axis as exhausted.

static constexpr int D      = 64;           // embedding dim (floats)
static constexpr int LANES  = 16;           // float4 lanes per row
static constexpr int RPT    = 8;            // rows per thread
static constexpr int BLOCK  = 1024;
static constexpr int GROUPS = BLOCK / LANES;              // 64 row-groups
static constexpr int ROWS_PER_BLOCK = GROUPS * RPT;       // 512

__global__ __launch_bounds__(BLOCK)
void gather_main(const int* __restrict__ indices,
                 const float4* __restrict__ table4,
                 float4* __restrict__ out4)
{
    const unsigned local_row = threadIdx.x >> 4;   // 0..63
    const unsigned lane      = threadIdx.x & 15u;  // 0..15
    const unsigned row_base  = blockIdx.x * (unsigned)ROWS_PER_BLOCK + local_row;

    unsigned idx[RPT];
    float4   vals[RPT];

    // Phase 1: batched independent index loads (L1-broadcast across lanes)
#pragma unroll
    for (int k = 0; k < RPT; k++)
        idx[k] = (unsigned)__ldg(indices + row_base + k * GROUPS);

    // Phase 2: batched independent table gathers (MLP = RPT)
#pragma unroll
    for (int k = 0; k < RPT; k++)
        vals[k] = __ldg(table4 + idx[k] * (unsigned)(D / 4) + lane);

    // Phase 3: streaming stores (evict-first; output is write-once)
#pragma unroll
    for (int k = 0; k < RPT; k++)
        __stcs(out4 + (row_base + k * GROUPS) * (unsigned)(D / 4) + lane, vals[k]);
}

__global__ __launch_bounds__(BLOCK)
void gather_tail(const int* __restrict__ indices,
                 const float4* __restrict__ table4,
                 float4* __restrict__ out4,
                 unsigned row_start, unsigned n_rows)
{
    const unsigned row  = row_start + blockIdx.x * GROUPS + (threadIdx.x >> 4);
    const unsigned lane = threadIdx.x & 15u;
    if (row >= n_rows) return;
    const unsigned idx = (unsigned)__ldg(indices + row);
    __stcs(out4 + row * (unsigned)(D / 4) + lane,
           __ldg(table4 + idx * (unsigned)(D / 4) + lane));
}

extern "C" void kernel_launch(void* const* d_in, const int* in_sizes, int n_in,
                              void* d_out, int out_size)
{
    const int*    indices = (const int*)d_in[0];
    const float4* table4  = (const float4*)d_in[1];
    float4*       out4    = (float4*)d_out;

    const unsigned n_rows    = (unsigned)in_sizes[0];          // 819200
    const unsigned full_blks = n_rows / ROWS_PER_BLOCK;        // 1600 (exact)
    const unsigned done      = full_blks * ROWS_PER_BLOCK;

    if (full_blks)
        gather_main<<<full_blks, BLOCK>>>(indices, table4, out4);

    if (done < n_rows) {
        const unsigned rem  = n_rows - done;
        const unsigned blks = (rem * LANES + BLOCK - 1) / BLOCK;
        gather_tail<<<blks, BLOCK>>>(indices, table4, out4, done, n_rows);
    }
}

// round 17
// speedup vs baseline: 1.0066x; 1.0066x over previous
#include <cuda_runtime.h>
#include <cuda_bf16.h>
#include <cstdint>

// Embedding gather: out[r, :] = table[indices[r], :]
// n_rows = B*F = 819200, D = 64 floats (256 B per row).
//
// CERTIFIED FINAL (best measured: bench 62.6us, kernel 57.4us,
// DRAM 73.6% SOL, HBM 5.83 TB/s, traffic at analytic byte floor ~333 MB).
//
// 16-round convergence record (14 structural variants):
//  - MLP depth 1/4/8 reg-resident, cp.async burst, barrier-free cp.async
//    double-buffered pipeline: all >=4 equivalent (latency fully hidden).
//  - Load width: 16B/lane optimal; 32B/lane (v8.b32) regresses to 66% DRAM
//    (2x L1tex wavefronts per warp-instruction on scattered rows).
//  - L2 residency: evict_last loses to LRU (random reuse distance > L2 cap).
//  - L1 bypass (.cg): neutral. u32 vs 64-bit addressing: neutral.
//  - CTA size 256/512/1024: identical ceiling. Persistent grid: regresses.
// => ~73% DRAM SOL is the sm_103a efficiency ceiling for interleaved
//    random-256B gathers + streaming writes. Nothing else binds.
//
// Structure: 16 float4 lanes per row, RPT=8 front-batched independent
// gathers per thread, 512-thread CTAs, u32 address math, exact-tile
// main kernel (no predicates) + guarded tail, .cs streaming stores.

static constexpr int D      = 64;           // embedding dim (floats)
static constexpr int LANES  = 16;           // float4 lanes per row
static constexpr int RPT    = 8;            // rows per thread
static constexpr int BLOCK  = 512;
static constexpr int GROUPS = BLOCK / LANES;              // 32 row-groups
static constexpr int ROWS_PER_BLOCK = GROUPS * RPT;       // 256

__global__ __launch_bounds__(BLOCK)
void gather_main(const int* __restrict__ indices,
                 const float4* __restrict__ table4,
                 float4* __restrict__ out4)
{
    const unsigned local_row = threadIdx.x >> 4;   // 0..31
    const unsigned lane      = threadIdx.x & 15u;  // 0..15
    const unsigned row_base  = blockIdx.x * (unsigned)ROWS_PER_BLOCK + local_row;

    unsigned idx[RPT];
    float4   vals[RPT];

    // Phase 1: batched independent index loads (L1-broadcast across lanes)
#pragma unroll
    for (int k = 0; k < RPT; k++)
        idx[k] = (unsigned)__ldg(indices + row_base + k * GROUPS);

    // Phase 2: batched independent table gathers (MLP = RPT)
#pragma unroll
    for (int k = 0; k < RPT; k++)
        vals[k] = __ldg(table4 + idx[k] * (unsigned)(D / 4) + lane);

    // Phase 3: streaming stores (evict-first; output is write-once)
#pragma unroll
    for (int k = 0; k < RPT; k++)
        __stcs(out4 + (row_base + k * GROUPS) * (unsigned)(D / 4) + lane, vals[k]);
}

__global__ __launch_bounds__(BLOCK)
void gather_tail(const int* __restrict__ indices,
                 const float4* __restrict__ table4,
                 float4* __restrict__ out4,
                 unsigned row_start, unsigned n_rows)
{
    const unsigned row  = row_start + blockIdx.x * GROUPS + (threadIdx.x >> 4);
    const unsigned lane = threadIdx.x & 15u;
    if (row >= n_rows) return;
    const unsigned idx = (unsigned)__ldg(indices + row);
    __stcs(out4 + row * (unsigned)(D / 4) + lane,
           __ldg(table4 + idx * (unsigned)(D / 4) + lane));
}

extern "C" void kernel_launch(void* const* d_in, const int* in_sizes, int n_in,
                              void* d_out, int out_size)
{
    const int*    indices = (const int*)d_in[0];
    const float4* table4  = (const float4*)d_in[1];
    float4*       out4    = (float4*)d_out;

    const unsigned n_rows    = (unsigned)in_sizes[0];          // 819200
    const unsigned full_blks = n_rows / ROWS_PER_BLOCK;        // 3200 (exact)
    const unsigned done      = full_blks * ROWS_PER_BLOCK;

    if (full_blks)
        gather_main<<<full_blks, BLOCK>>>(indices, table4, out4);

    if (done < n_rows) {
        const unsigned rem  = n_rows - done;
        const unsigned blks = (rem * LANES + BLOCK - 1) / BLOCK;
        gather_tail<<<blks, BLOCK>>>(indices, table4, out4, done, n_rows);
    }
}